// round 16
// baseline (speedup 1.0000x reference)
#include <cuda_runtime.h>
#include <cuda_bf16.h>
#include <cstdint>

// adaptive_avg_pool2d(x[32,2048,28,28], 7) -> out[32,49,2048]
// linspace(0,28,8) = 0,4,...,28 => exact uniform 4x4 windows.
//
// R16: last untested grid point — 128-thread blocks (TILE_C=4, 16384
// blocks). launch_bounds(128,12) gives the SAME 48 warps/SM and SAME
// 42-reg budget as the proven (256,6) config, so the 7xLDG.128 front
// batch (MLP=7, regs=38) is preserved; only the scheduler tail quantum
// halves. R11 measured per-block fixed cost as non-binding, so the
// downside of more blocks is nil.
//
// Frozen core (R13, kernel 32.8-33.2us across 3 runs, ~6.45 TB/s ~= 95%+
// of the B300 LTS/HBM achievable ceiling):
//  - one channel per warp; 7xLDG.128 front batch with __ldcs
//  - raw horizontal 4-sums -> per-warp smem stage; warp-local vertical
//    reduce, no atomics; single *0.0625 at the end
//  - loop-free writeout, PLAIN stores (L2 partial-line merging)
// Rejected by measurement: smem atomics (R1-2), single-wave grid (R4),
// cp.async (R7), reg-cap 36 (R8), __stcs writes (R9/R10), 512-thr blocks
// (R11), STG.128 epilogue (R14, neutral).

#define CCH    2048
#define HW     784
#define TILE_C 4
#define ACC_STRIDE 57    // odd stride: conflict-free transposed readout
#define STG_STRIDE 200   // per-warp stage stride

__global__ __launch_bounds__(128, 12)
void upp_pool_kernel(const float* __restrict__ x, float* __restrict__ out) {
    __shared__ float stage[4 * STG_STRIDE];     // 3200 B
    __shared__ float acc[TILE_C * ACC_STRIDE];  // 912 B

    const int tid  = threadIdx.x;
    const int warp = tid >> 5;     // = c_local: one channel per warp (0..3)
    const int lane = tid & 31;

    const float4* __restrict__ plane =
        reinterpret_cast<const float4*>(
            x + ((size_t)(blockIdx.y * CCH + blockIdx.x * TILE_C + warp)) * HW)
        + lane;

    // Phase 1: front-batch ALL 7 LDG.128 (MLP=7), streaming (evict-first).
    const float4 v0 = __ldcs(plane +   0);
    const float4 v1 = __ldcs(plane +  32);
    const float4 v2 = __ldcs(plane +  64);
    const float4 v3 = __ldcs(plane +  96);
    const float4 v4 = __ldcs(plane + 128);
    const float4 v5 = __ldcs(plane + 160);
    float4 v6 = make_float4(0.f, 0.f, 0.f, 0.f);
    if (lane < 4) v6 = __ldcs(plane + 192);

    // Raw horizontal 4-sums -> per-warp stage (scale deferred to phase 2)
    const int wbase = warp * STG_STRIDE + lane;
    stage[wbase +   0] = (v0.x + v0.y) + (v0.z + v0.w);
    stage[wbase +  32] = (v1.x + v1.y) + (v1.z + v1.w);
    stage[wbase +  64] = (v2.x + v2.y) + (v2.z + v2.w);
    stage[wbase +  96] = (v3.x + v3.y) + (v3.z + v3.w);
    stage[wbase + 128] = (v4.x + v4.y) + (v4.z + v4.w);
    stage[wbase + 160] = (v5.x + v5.y) + (v5.z + v5.w);
    if (lane < 4)
        stage[wbase + 192] = (v6.x + v6.y) + (v6.z + v6.w);
    __syncwarp();

    // Phase 2: vertical reduce over 4 rows per bin; single scale at the end.
    {
        const int o0 = warp * STG_STRIDE + 28 * (lane / 7) + (lane % 7);
        acc[warp * ACC_STRIDE + lane] =
            ((stage[o0] + stage[o0 + 7]) +
             (stage[o0 + 14] + stage[o0 + 21])) * 0.0625f;
    }
    if (lane < 17) {
        const int b1 = lane + 32;
        const int o1 = warp * STG_STRIDE + 28 * (b1 / 7) + (b1 % 7);
        acc[warp * ACC_STRIDE + b1] =
            ((stage[o1] + stage[o1 + 7]) +
             (stage[o1 + 14] + stage[o1 + 21])) * 0.0625f;
    }
    __syncthreads();

    // Writeout, loop-free: 49 p-rows x 4 channels = 98 STG.64.
    // Thread t (<98): p = t>>1, channel pair c = 2*(t&1). Plain stores:
    // partial-line sectors linger in L2 and merge with neighbor blocks.
    if (tid < 98) {
        const int p = tid >> 1;
        const int c = (tid & 1) * 2;
        const float2 w = make_float2(acc[c * ACC_STRIDE + p],
                                     acc[(c + 1) * ACC_STRIDE + p]);
        float2* __restrict__ ob = reinterpret_cast<float2*>(
            out + (size_t)blockIdx.y * 49 * CCH + blockIdx.x * TILE_C
                + p * CCH + c);
        *ob = w;
    }
}

extern "C" void kernel_launch(void* const* d_in, const int* in_sizes, int n_in,
                              void* d_out, int out_size) {
    const float* x = (const float*)d_in[0];
    float* out = (float*)d_out;
    dim3 grid(CCH / TILE_C, 32);   // (512, 32) = 16384 blocks
    upp_pool_kernel<<<grid, 128>>>(x, out);
}

// round 17
// speedup vs baseline: 1.0202x; 1.0202x over previous
#include <cuda_runtime.h>
#include <cuda_bf16.h>
#include <cstdint>

// adaptive_avg_pool2d(x[32,2048,28,28], 7) -> out[32,49,2048]
// linspace(0,28,8) = 0,4,...,28 => exact uniform 4x4 windows.
//
// FINAL (= R13, best measured kernel dur 32.83us; reproduced 32.93/33.15.
// 6.45 TB/s on 218 MB irreducible single-touch traffic = >=95% of the B300
// path-independent LTS/HBM achievable ceiling (~6300 B/cyc); the 8 TB/s
// spec is unreachable by any load path on this part).
//
// Design, each element measured-in across 16 rounds:
//  - 8192 short 256-thread blocks: fine granularity -> no scheduler drain
//    tail. Sweep complete: 128thr ~= 256thr (R16) > 512thr (R11) >>
//    single-wave (R4).
//  - One channel per warp; 7xLDG.128 front batch (MLP=7) with __ldcs
//    (touch-once reads: evict-first correct). launch_bounds(256,6) = 42-reg
//    budget; tighter caps made ptxas break the batch (R8). regs=38.
//  - Raw horizontal 4-sums -> per-warp smem stage (plain STS, conflict-
//    free); warp-local vertical 4-row reduce -- NO atomics (removing smem
//    atomicAdd was the 2x win, R3); single *0.0625 at the end.
//  - Loop-free writeout: 196 STG.64, PLAIN stores (default evict) so 32B
//    partial-line sectors merge with adjacent blocks' writes in L2 before
//    writeback (beat __stcs writes: R13 vs R10).
// Rejected by measurement: smem atomics (R1-2), single-wave grid (R4),
// cp.async/LDGSTS (R7), reg-cap 36 (R8), __stcs writes (R9/R10),
// 512-thr blocks (R11), STG.128 epilogue (R14), 128-thr blocks (R16,
// neutral).

#define CCH    2048
#define HW     784
#define TILE_C 8
#define ACC_STRIDE 57    // odd stride: conflict-free transposed readout
#define STG_STRIDE 200   // per-warp stage stride

__global__ __launch_bounds__(256, 6)
void upp_pool_kernel(const float* __restrict__ x, float* __restrict__ out) {
    __shared__ float stage[8 * STG_STRIDE];     // 6400 B
    __shared__ float acc[TILE_C * ACC_STRIDE];  // 1824 B

    const int tid  = threadIdx.x;
    const int warp = tid >> 5;     // = c_local: one channel per warp
    const int lane = tid & 31;

    const float4* __restrict__ plane =
        reinterpret_cast<const float4*>(
            x + ((size_t)(blockIdx.y * CCH + blockIdx.x * TILE_C + warp)) * HW)
        + lane;

    // Phase 1: front-batch ALL 7 LDG.128 (MLP=7), streaming (evict-first).
    const float4 v0 = __ldcs(plane +   0);
    const float4 v1 = __ldcs(plane +  32);
    const float4 v2 = __ldcs(plane +  64);
    const float4 v3 = __ldcs(plane +  96);
    const float4 v4 = __ldcs(plane + 128);
    const float4 v5 = __ldcs(plane + 160);
    float4 v6 = make_float4(0.f, 0.f, 0.f, 0.f);
    if (lane < 4) v6 = __ldcs(plane + 192);

    // Raw horizontal 4-sums -> per-warp stage (scale deferred to phase 2)
    const int wbase = warp * STG_STRIDE + lane;
    stage[wbase +   0] = (v0.x + v0.y) + (v0.z + v0.w);
    stage[wbase +  32] = (v1.x + v1.y) + (v1.z + v1.w);
    stage[wbase +  64] = (v2.x + v2.y) + (v2.z + v2.w);
    stage[wbase +  96] = (v3.x + v3.y) + (v3.z + v3.w);
    stage[wbase + 128] = (v4.x + v4.y) + (v4.z + v4.w);
    stage[wbase + 160] = (v5.x + v5.y) + (v5.z + v5.w);
    if (lane < 4)
        stage[wbase + 192] = (v6.x + v6.y) + (v6.z + v6.w);
    __syncwarp();

    // Phase 2: vertical reduce over 4 rows per bin; single scale at the end.
    {
        const int o0 = warp * STG_STRIDE + 28 * (lane / 7) + (lane % 7);
        acc[warp * ACC_STRIDE + lane] =
            ((stage[o0] + stage[o0 + 7]) +
             (stage[o0 + 14] + stage[o0 + 21])) * 0.0625f;
    }
    if (lane < 17) {
        const int b1 = lane + 32;
        const int o1 = warp * STG_STRIDE + 28 * (b1 / 7) + (b1 % 7);
        acc[warp * ACC_STRIDE + b1] =
            ((stage[o1] + stage[o1 + 7]) +
             (stage[o1 + 14] + stage[o1 + 21])) * 0.0625f;
    }
    __syncthreads();

    // Writeout, loop-free: 49 p-rows x 8 channels = 196 STG.64.
    // Thread t (<196): p = t/4, channel pair c = 2*(t&3). Plain stores:
    // partial-line sectors linger in L2 and merge with neighbor blocks.
    if (tid < 196) {
        const int p = tid >> 2;
        const int c = (tid & 3) * 2;
        const float2 w = make_float2(acc[c * ACC_STRIDE + p],
                                     acc[(c + 1) * ACC_STRIDE + p]);
        float2* __restrict__ ob = reinterpret_cast<float2*>(
            out + (size_t)blockIdx.y * 49 * CCH + blockIdx.x * TILE_C
                + p * CCH + c);
        *ob = w;
    }
}

extern "C" void kernel_launch(void* const* d_in, const int* in_sizes, int n_in,
                              void* d_out, int out_size) {
    const float* x = (const float*)d_in[0];
    float* out = (float*)d_out;
    dim3 grid(CCH / TILE_C, 32);   // (256, 32) = 8192 short blocks
    upp_pool_kernel<<<grid, 256>>>(x, out);
}